// round 16
// baseline (speedup 1.0000x reference)
#include <cuda_runtime.h>

// Tiny MLP: out = L3( relu(L2)^100( relu(L1(x)) ) ), weights shared.
// out(x) is piecewise-constant (elements converge to 1 of 4 fixed points).
//   1) lut_fused: interval arithmetic certifies 65536 x-intervals; each
//      block detects transitions LOCALLY in smem (thread 0 redundantly
//      computes the cross-block boundary interval); ~10 appending threads
//      fence; last block sorts + builds the breakpoint table.
//   2) main (R12-proven): breakpoints staged to SMEM once per block;
//      predicated selects -> pure streaming. NaN/out-of-range -> exact
//      100-iter fallback; >64 transitions -> LUT gather path.

#define TPB 256
#define NLUT 65536
#define XMIN (-8.0f)
#define XSPAN (16.0f)
#define MAXBP 64

__device__ float d_lut[NLUT];
__device__ int   d_cnt;    // zero-init at load; last block re-zeros each replay
__device__ int   d_done;
__device__ int   d_idx[MAXBP];
__device__ int   d_nbp;
__device__ float d_bpx[MAXBP];
__device__ float d_bpv[MAXBP + 1];

struct Net {
    float w10, w11, b10, b11;
    float w200, w201, w210, w211, b20, b21;
    float w30, w31, b30;
    float p11_0, p11_1, p10_0, p01_1;
    float D11, D10, D01, D00;
};

__device__ __forceinline__ Net load_net(
    const float* w1, const float* b1, const float* w2, const float* b2,
    const float* w3, const float* b3)
{
    Net n;
    n.w10 = w1[0]; n.w11 = w1[1]; n.b10 = b1[0]; n.b11 = b1[1];
    n.w200 = w2[0]; n.w201 = w2[1]; n.w210 = w2[2]; n.w211 = w2[3];
    n.b20 = b2[0]; n.b21 = b2[1];
    n.w30 = w3[0]; n.w31 = w3[1]; n.b30 = b3[0];

    const float rsF = fmaxf(fabsf(n.w200) + fabsf(n.w210),
                            fabsf(n.w201) + fabsf(n.w211));
    const float a11 = 1.f - n.w200, a12 = -n.w210, a21 = -n.w201, a22 = 1.f - n.w211;
    const float det = a11 * a22 - a12 * a21;
    const float inv = 1.f / det;
    n.p11_0 = (a22 * n.b20 - a12 * n.b21) * inv;
    n.p11_1 = (a11 * n.b21 - a21 * n.b20) * inv;
    const float m11 = fminf(n.p11_0, n.p11_1);
    n.D11 = (m11 > 0.f && rsF <= 0.85f)
          ? fminf(0.9f * m11 / rsF, 0.25f) - 1e-5f : -1.f;
    const float gOne = rsF * fmaxf(rsF, 1.f);
    n.p10_0 = n.b20 / (1.f - n.w200);
    const float z1_10 = n.w201 * n.p10_0 + n.b21;
    const float m10 = fminf(n.p10_0, -z1_10);
    n.D10 = (m10 > 0.f) ? fminf(0.9f * m10 / gOne, 0.25f) - 1e-5f : -1.f;
    n.p01_1 = n.b21 / (1.f - n.w211);
    const float z0_01 = n.w210 * n.p01_1 + n.b20;
    const float m01 = fminf(n.p01_1, -z0_01);
    n.D01 = (m01 > 0.f) ? fminf(0.9f * m01 / gOne, 0.25f) - 1e-5f : -1.f;
    const float m00 = fminf(-n.b20, -n.b21);
    n.D00 = (m00 > 0.f) ? fminf(0.9f * m00 / rsF, 0.25f) - 1e-5f : -1.f;
    return n;
}

// Sound interval certification of x-interval j. Returns certified output
// value or NaN sentinel.
__device__ float interval_eval(int j, const Net& n)
{
    const float wdt = XSPAN / (float)NLUT;
    const float xl = XMIN + j * wdt, xh = xl + wdt;
    float t0 = fmaf(xl, n.w10, n.b10), t1 = fmaf(xh, n.w10, n.b10);
    float h0l = fmaxf(fminf(t0, t1), 0.f), h0h = fmaxf(fmaxf(t0, t1), 0.f);
    t0 = fmaf(xl, n.w11, n.b11); t1 = fmaf(xh, n.w11, n.b11);
    float h1l = fmaxf(fminf(t0, t1), 0.f), h1h = fmaxf(fmaxf(t0, t1), 0.f);

    float out = __int_as_float(0x7fc00000);  // NaN sentinel
    const float SL = 2e-6f;

    for (int t = 0; t < 48; t++) {
        bool c11 = (n.D11 > 0.f) & (h0l > n.p11_0 - n.D11) & (h0h < n.p11_0 + n.D11)
                                 & (h1l > n.p11_1 - n.D11) & (h1h < n.p11_1 + n.D11);
        bool c10 = (n.D10 > 0.f) & (h0l > n.p10_0 - n.D10) & (h0h < n.p10_0 + n.D10)
                                 & (h1h < n.D10);
        bool c01 = (n.D01 > 0.f) & (h1l > n.p01_1 - n.D01) & (h1h < n.p01_1 + n.D01)
                                 & (h0h < n.D01);
        bool c00 = (n.D00 > 0.f) & (h0h < n.D00) & (h1h < n.D00);
        if (c11) { out = fmaf(n.p11_0, n.w30, fmaf(n.p11_1, n.w31, n.b30)); break; }
        if (c10) { out = fmaf(n.p10_0, n.w30, n.b30); break; }
        if (c01) { out = fmaf(n.p01_1, n.w31, n.b30); break; }
        if (c00) { out = n.b30; break; }

        float z0l = fminf(n.w200 * h0l, n.w200 * h0h) + fminf(n.w210 * h1l, n.w210 * h1h) + n.b20 - SL;
        float z0h = fmaxf(n.w200 * h0l, n.w200 * h0h) + fmaxf(n.w210 * h1l, n.w210 * h1h) + n.b20 + SL;
        float z1l = fminf(n.w201 * h0l, n.w201 * h0h) + fminf(n.w211 * h1l, n.w211 * h1h) + n.b21 - SL;
        float z1h = fmaxf(n.w201 * h0l, n.w201 * h0h) + fmaxf(n.w211 * h1l, n.w211 * h1h) + n.b21 + SL;
        h0l = fmaxf(z0l, 0.f); h0h = fmaxf(z0h, 0.f);
        h1l = fmaxf(z1l, 0.f); h1h = fmaxf(z1h, 0.f);
    }
    return out;
}

__global__ void lut_fused(const float* __restrict__ w1, const float* __restrict__ b1,
                          const float* __restrict__ w2, const float* __restrict__ b2,
                          const float* __restrict__ w3, const float* __restrict__ b3)
{
    __shared__ float s_val[TPB + 1];
    __shared__ bool  s_last;
    int tid = threadIdx.x;
    int j = blockIdx.x * TPB + tid;

    Net net = load_net(w1, b1, w2, b2, w3, b3);

    float out = interval_eval(j, net);
    d_lut[j] = out;                         // needed only by gather fallback
    s_val[tid] = out;
    if (tid == 0) {
        int jn = blockIdx.x * TPB + TPB;    // cross-block boundary neighbor
        s_val[TPB] = (jn < NLUT) ? interval_eval(jn, net) : out;
    }
    __syncthreads();

    // Local transition detection (no global visibility needed).
    if (j < NLUT - 1) {
        float right = s_val[tid + 1];
        if (__float_as_int(out) != __float_as_int(right)) {
            int k = atomicAdd(&d_cnt, 1);
            if (k < MAXBP) d_idx[k] = j;
            __threadfence();                // ~10 appenders total: cheap
        }
    }
    __syncthreads();

    // Last-block-done: build the table.
    if (tid == 0) {
        __threadfence();
        int prev = atomicAdd(&d_done, 1);
        s_last = (prev == (int)gridDim.x - 1);
    }
    __syncthreads();
    if (!s_last) return;

    if (tid == 0) {
        int n = d_cnt;
        if (n > MAXBP) {
            d_nbp = -1;                     // gather path in main
        } else {
            for (int a = 1; a < n; a++) {   // insertion sort (tiny n)
                int key = d_idx[a];
                int b = a - 1;
                while (b >= 0 && d_idx[b] > key) { d_idx[b + 1] = d_idx[b]; b--; }
                d_idx[b + 1] = key;
            }
            const float wdt = XSPAN / (float)NLUT;
            d_bpv[0] = d_lut[0];
            for (int k = 0; k < n; k++) {
                d_bpx[k] = XMIN + (float)(d_idx[k] + 1) * wdt;   // exact fp32
                d_bpv[k + 1] = d_lut[d_idx[k] + 1];
            }
            d_nbp = n;
        }
        d_cnt = 0;                          // reset for next graph replay
        d_done = 0;
        __threadfence();
    }
}

// Exact per-element fallback: 100 iterations with bitwise fixed-point exit.
__device__ __forceinline__ float exact_eval(
    float x,
    float w10, float w11, float b10, float b11,
    float w200, float w201, float w210, float w211,
    float b20, float b21, float w30, float w31, float b30)
{
    float h0 = fmaxf(fmaf(x, w10, b10), 0.f);
    float h1 = fmaxf(fmaf(x, w11, b11), 0.f);
#pragma unroll 1
    for (int t = 0; t < 100; t++) {
        float z0 = fmaf(h0, w200, fmaf(h1, w210, b20));
        float z1 = fmaf(h0, w201, fmaf(h1, w211, b21));
        float n0 = fmaxf(z0, 0.f);
        float n1 = fmaxf(z1, 0.f);
        if (n0 == h0 && n1 == h1) break;
        h0 = n0; h1 = n1;
    }
    return fmaf(h0, w30, fmaf(h1, w31, b30));
}

__global__ __launch_bounds__(TPB) void net_39204461478865_kernel(
    const float4* __restrict__ x4,
    const float* __restrict__ w1, const float* __restrict__ b1,
    const float* __restrict__ w2, const float* __restrict__ b2,
    const float* __restrict__ w3, const float* __restrict__ b3,
    float4* __restrict__ out4, int n4)
{
    __shared__ float s_bpx[MAXBP];
    __shared__ float s_bpv[MAXBP + 1];
    __shared__ int   s_nbp;

    int tid = threadIdx.x;
    if (tid == 0) s_nbp = d_nbp;
    if (tid < MAXBP) s_bpx[tid] = d_bpx[tid];
    if (tid < MAXBP + 1) s_bpv[tid] = d_bpv[tid];
    __syncthreads();

    int i = blockIdx.x * TPB + tid;
    if (i >= n4) return;

    float4 xin = x4[i];
    float xs[4] = {xin.x, xin.y, xin.z, xin.w};
    float v[4];
    bool ok[4];
    bool bad = false;

    int nbp = s_nbp;
    if (nbp >= 0) {
        float v0 = s_bpv[0];
        v[0] = v0; v[1] = v0; v[2] = v0; v[3] = v0;
#pragma unroll 1
        for (int k = 0; k < nbp; k++) {
            float bx = s_bpx[k];
            float bv = s_bpv[k + 1];
#pragma unroll
            for (int e = 0; e < 4; e++)
                v[e] = (xs[e] >= bx) ? bv : v[e];
        }
    } else {
        const float scale = (float)NLUT / XSPAN;
#pragma unroll
        for (int e = 0; e < 4; e++) {
            int jj = __float2int_rd((xs[e] - XMIN) * scale);
            jj = max(0, min(NLUT - 1, jj));
            v[e] = d_lut[jj];
        }
    }

#pragma unroll
    for (int e = 0; e < 4; e++) {
        bool in = (xs[e] >= XMIN) & (xs[e] < XMIN + XSPAN);
        ok[e] = in & (v[e] == v[e]);         // NaN sentinel -> false
        bad |= !ok[e];
    }

    if (bad) {
        const float w10 = __ldg(&w1[0]), w11 = __ldg(&w1[1]);
        const float b10 = __ldg(&b1[0]), b11 = __ldg(&b1[1]);
        const float w200 = __ldg(&w2[0]), w201 = __ldg(&w2[1]);
        const float w210 = __ldg(&w2[2]), w211 = __ldg(&w2[3]);
        const float b20 = __ldg(&b2[0]), b21 = __ldg(&b2[1]);
        const float w30 = __ldg(&w3[0]), w31 = __ldg(&w3[1]);
        const float b30 = __ldg(&b3[0]);
#pragma unroll
        for (int e = 0; e < 4; e++) {
            if (!ok[e]) {
                v[e] = exact_eval(xs[e], w10, w11, b10, b11,
                                  w200, w201, w210, w211,
                                  b20, b21, w30, w31, b30);
            }
        }
    }

    float4 o;
    o.x = v[0]; o.y = v[1]; o.z = v[2]; o.w = v[3];
    out4[i] = o;
}

extern "C" void kernel_launch(void* const* d_in, const int* in_sizes, int n_in,
                              void* d_out, int out_size)
{
    const float* x  = (const float*)d_in[0];
    const float* w1 = (const float*)d_in[1];
    const float* b1 = (const float*)d_in[2];
    const float* w2 = (const float*)d_in[3];
    const float* b2 = (const float*)d_in[4];
    const float* w3 = (const float*)d_in[5];
    const float* b3 = (const float*)d_in[6];

    int n  = in_sizes[0];
    int n4 = n / 4;
    int blocks = (n4 + TPB - 1) / TPB;

    lut_fused<<<NLUT / TPB, TPB>>>(w1, b1, w2, b2, w3, b3);
    net_39204461478865_kernel<<<blocks, TPB>>>(
        (const float4*)x, w1, b1, w2, b2, w3, b3, (float4*)d_out, n4);
}

// round 17
// speedup vs baseline: 1.1777x; 1.1777x over previous
#include <cuda_runtime.h>

// Tiny MLP: out = L3( relu(L2)^100( relu(L1(x)) ) ), weights shared.
// R12-proven pipeline (best measured config), prepass shrunk:
//   1) lut_prepass: interval arithmetic certifies 32768 x-intervals (<=32 steps).
//   2) bp_scan:     parallel transition scan (atomic append).
//   3) bp_build:    1 thread sorts ~10 breakpoints, builds table.
//   4) main:        breakpoints staged to SMEM once/block; predicated
//                   selects -> pure streaming. NaN/out-of-range -> exact
//                   100-iter fallback; >64 transitions -> LUT gather path.

#define TPB 256
#define NLUT 32768
#define XMIN (-8.0f)
#define XSPAN (16.0f)
#define MAXBP 64

__device__ float d_lut[NLUT];
__device__ int   d_cnt;
__device__ int   d_idx[MAXBP];
__device__ int   d_nbp;
__device__ float d_bpx[MAXBP];
__device__ float d_bpv[MAXBP + 1];

__global__ void lut_prepass(const float* __restrict__ w1, const float* __restrict__ b1,
                            const float* __restrict__ w2, const float* __restrict__ b2,
                            const float* __restrict__ w3, const float* __restrict__ b3)
{
    int j = blockIdx.x * blockDim.x + threadIdx.x;
    if (j == 0) d_cnt = 0;                   // reset for this graph replay
    if (j >= NLUT) return;

    const float w10 = w1[0], w11 = w1[1], b10 = b1[0], b11 = b1[1];
    const float w200 = w2[0], w201 = w2[1], w210 = w2[2], w211 = w2[3];
    const float b20 = b2[0], b21 = b2[1];
    const float w30 = w3[0], w31 = w3[1], b30 = b3[0];

    const float rsF = fmaxf(fabsf(w200) + fabsf(w210), fabsf(w201) + fabsf(w211));

    const float a11 = 1.f - w200, a12 = -w210, a21 = -w201, a22 = 1.f - w211;
    const float det = a11 * a22 - a12 * a21;
    const float inv = 1.f / det;
    const float p11_0 = (a22 * b20 - a12 * b21) * inv;
    const float p11_1 = (a11 * b21 - a21 * b20) * inv;
    const float m11 = fminf(p11_0, p11_1);
    const float D11 = (m11 > 0.f && rsF <= 0.85f)
                    ? fminf(0.9f * m11 / rsF, 0.25f) - 1e-5f : -1.f;
    const float gOne = rsF * fmaxf(rsF, 1.f);
    const float p10_0 = b20 / (1.f - w200);
    const float z1_10 = w201 * p10_0 + b21;
    const float m10 = fminf(p10_0, -z1_10);
    const float D10 = (m10 > 0.f) ? fminf(0.9f * m10 / gOne, 0.25f) - 1e-5f : -1.f;
    const float p01_1 = b21 / (1.f - w211);
    const float z0_01 = w210 * p01_1 + b20;
    const float m01 = fminf(p01_1, -z0_01);
    const float D01 = (m01 > 0.f) ? fminf(0.9f * m01 / gOne, 0.25f) - 1e-5f : -1.f;
    const float m00 = fminf(-b20, -b21);
    const float D00 = (m00 > 0.f) ? fminf(0.9f * m00 / rsF, 0.25f) - 1e-5f : -1.f;

    const float wdt = XSPAN / (float)NLUT;
    const float xl = XMIN + j * wdt, xh = xl + wdt;
    float t0 = fmaf(xl, w10, b10), t1 = fmaf(xh, w10, b10);
    float h0l = fmaxf(fminf(t0, t1), 0.f), h0h = fmaxf(fmaxf(t0, t1), 0.f);
    t0 = fmaf(xl, w11, b11); t1 = fmaf(xh, w11, b11);
    float h1l = fmaxf(fminf(t0, t1), 0.f), h1h = fmaxf(fmaxf(t0, t1), 0.f);

    float out = __int_as_float(0x7fc00000);  // NaN sentinel
    const float SL = 2e-6f;

    for (int t = 0; t < 32; t++) {
        bool c11 = (D11 > 0.f) & (h0l > p11_0 - D11) & (h0h < p11_0 + D11)
                               & (h1l > p11_1 - D11) & (h1h < p11_1 + D11);
        bool c10 = (D10 > 0.f) & (h0l > p10_0 - D10) & (h0h < p10_0 + D10)
                               & (h1h < D10);
        bool c01 = (D01 > 0.f) & (h1l > p01_1 - D01) & (h1h < p01_1 + D01)
                               & (h0h < D01);
        bool c00 = (D00 > 0.f) & (h0h < D00) & (h1h < D00);
        if (c11) { out = fmaf(p11_0, w30, fmaf(p11_1, w31, b30)); break; }
        if (c10) { out = fmaf(p10_0, w30, b30); break; }
        if (c01) { out = fmaf(p01_1, w31, b30); break; }
        if (c00) { out = b30; break; }

        float z0l = fminf(w200 * h0l, w200 * h0h) + fminf(w210 * h1l, w210 * h1h) + b20 - SL;
        float z0h = fmaxf(w200 * h0l, w200 * h0h) + fmaxf(w210 * h1l, w210 * h1h) + b20 + SL;
        float z1l = fminf(w201 * h0l, w201 * h0h) + fminf(w211 * h1l, w211 * h1h) + b21 - SL;
        float z1h = fmaxf(w201 * h0l, w201 * h0h) + fmaxf(w211 * h1l, w211 * h1h) + b21 + SL;
        h0l = fmaxf(z0l, 0.f); h0h = fmaxf(z0h, 0.f);
        h1l = fmaxf(z1l, 0.f); h1h = fmaxf(z1h, 0.f);
    }
    d_lut[j] = out;
}

// Parallel transition scan: one thread per adjacent LUT pair.
__global__ void bp_scan()
{
    int j = blockIdx.x * blockDim.x + threadIdx.x;
    if (j >= NLUT - 1) return;
    if (__float_as_int(d_lut[j]) != __float_as_int(d_lut[j + 1])) {
        int k = atomicAdd(&d_cnt, 1);
        if (k < MAXBP) d_idx[k] = j;
    }
}

// Single-thread table build (n is ~10).
__global__ void bp_build()
{
    int n = d_cnt;
    if (n > MAXBP) { d_nbp = -1; return; }
    for (int a = 1; a < n; a++) {            // insertion sort
        int key = d_idx[a];
        int b = a - 1;
        while (b >= 0 && d_idx[b] > key) { d_idx[b + 1] = d_idx[b]; b--; }
        d_idx[b + 1] = key;
    }
    const float wdt = XSPAN / (float)NLUT;
    d_bpv[0] = d_lut[0];
    for (int k = 0; k < n; k++) {
        d_bpx[k] = XMIN + (float)(d_idx[k] + 1) * wdt;   // exact fp32 boundary
        d_bpv[k + 1] = d_lut[d_idx[k] + 1];
    }
    d_nbp = n;
}

// Exact per-element fallback: 100 iterations with bitwise fixed-point exit.
__device__ __forceinline__ float exact_eval(
    float x,
    float w10, float w11, float b10, float b11,
    float w200, float w201, float w210, float w211,
    float b20, float b21, float w30, float w31, float b30)
{
    float h0 = fmaxf(fmaf(x, w10, b10), 0.f);
    float h1 = fmaxf(fmaf(x, w11, b11), 0.f);
#pragma unroll 1
    for (int t = 0; t < 100; t++) {
        float z0 = fmaf(h0, w200, fmaf(h1, w210, b20));
        float z1 = fmaf(h0, w201, fmaf(h1, w211, b21));
        float n0 = fmaxf(z0, 0.f);
        float n1 = fmaxf(z1, 0.f);
        if (n0 == h0 && n1 == h1) break;
        h0 = n0; h1 = n1;
    }
    return fmaf(h0, w30, fmaf(h1, w31, b30));
}

__global__ __launch_bounds__(TPB) void net_39204461478865_kernel(
    const float4* __restrict__ x4,
    const float* __restrict__ w1, const float* __restrict__ b1,
    const float* __restrict__ w2, const float* __restrict__ b2,
    const float* __restrict__ w3, const float* __restrict__ b3,
    float4* __restrict__ out4, int n4)
{
    __shared__ float s_bpx[MAXBP];
    __shared__ float s_bpv[MAXBP + 1];
    __shared__ int   s_nbp;

    int tid = threadIdx.x;
    if (tid == 0) s_nbp = d_nbp;
    if (tid < MAXBP) s_bpx[tid] = d_bpx[tid];
    if (tid < MAXBP + 1) s_bpv[tid] = d_bpv[tid];
    __syncthreads();

    int i = blockIdx.x * TPB + tid;
    if (i >= n4) return;

    float4 xin = x4[i];
    float xs[4] = {xin.x, xin.y, xin.z, xin.w};
    float v[4];
    bool ok[4];
    bool bad = false;

    int nbp = s_nbp;
    if (nbp >= 0) {
        float v0 = s_bpv[0];
        v[0] = v0; v[1] = v0; v[2] = v0; v[3] = v0;
#pragma unroll 1
        for (int k = 0; k < nbp; k++) {
            float bx = s_bpx[k];
            float bv = s_bpv[k + 1];
#pragma unroll
            for (int e = 0; e < 4; e++)
                v[e] = (xs[e] >= bx) ? bv : v[e];
        }
    } else {
        const float scale = (float)NLUT / XSPAN;
#pragma unroll
        for (int e = 0; e < 4; e++) {
            int jj = __float2int_rd((xs[e] - XMIN) * scale);
            jj = max(0, min(NLUT - 1, jj));
            v[e] = d_lut[jj];
        }
    }

#pragma unroll
    for (int e = 0; e < 4; e++) {
        bool in = (xs[e] >= XMIN) & (xs[e] < XMIN + XSPAN);
        ok[e] = in & (v[e] == v[e]);         // NaN sentinel -> false
        bad |= !ok[e];
    }

    if (bad) {
        const float w10 = __ldg(&w1[0]), w11 = __ldg(&w1[1]);
        const float b10 = __ldg(&b1[0]), b11 = __ldg(&b1[1]);
        const float w200 = __ldg(&w2[0]), w201 = __ldg(&w2[1]);
        const float w210 = __ldg(&w2[2]), w211 = __ldg(&w2[3]);
        const float b20 = __ldg(&b2[0]), b21 = __ldg(&b2[1]);
        const float w30 = __ldg(&w3[0]), w31 = __ldg(&w3[1]);
        const float b30 = __ldg(&b3[0]);
#pragma unroll
        for (int e = 0; e < 4; e++) {
            if (!ok[e]) {
                v[e] = exact_eval(xs[e], w10, w11, b10, b11,
                                  w200, w201, w210, w211,
                                  b20, b21, w30, w31, b30);
            }
        }
    }

    float4 o;
    o.x = v[0]; o.y = v[1]; o.z = v[2]; o.w = v[3];
    out4[i] = o;
}

extern "C" void kernel_launch(void* const* d_in, const int* in_sizes, int n_in,
                              void* d_out, int out_size)
{
    const float* x  = (const float*)d_in[0];
    const float* w1 = (const float*)d_in[1];
    const float* b1 = (const float*)d_in[2];
    const float* w2 = (const float*)d_in[3];
    const float* b2 = (const float*)d_in[4];
    const float* w3 = (const float*)d_in[5];
    const float* b3 = (const float*)d_in[6];

    int n  = in_sizes[0];
    int n4 = n / 4;
    int blocks = (n4 + TPB - 1) / TPB;

    lut_prepass<<<NLUT / TPB, TPB>>>(w1, b1, w2, b2, w3, b3);
    bp_scan<<<NLUT / TPB, TPB>>>();
    bp_build<<<1, 1>>>();
    net_39204461478865_kernel<<<blocks, TPB>>>(
        (const float4*)x, w1, b1, w2, b2, w3, b3, (float4*)d_out, n4);
}